// round 6
// baseline (speedup 1.0000x reference)
#include <cuda_runtime.h>
#include <cstdint>
#include <math.h>

// ---------------------------------------------------------------------------
// Problem constants
// ---------------------------------------------------------------------------
#define SEQ     4096
#define DIM     2048
#define NHEADS  16
#define HDIM    128
#define QKV_N   6144

// ---------------------------------------------------------------------------
// Scratch (device globals; allocation is forbidden)
// ---------------------------------------------------------------------------
__device__ __align__(16) float g_xr    [(size_t)SEQ * DIM];
__device__ __align__(16) float g_wqkvT [(size_t)QKV_N * DIM];
__device__ __align__(16) float g_woT   [(size_t)DIM * DIM];
__device__ __align__(16) float g_xqkv  [(size_t)SEQ * QKV_N];
__device__ __align__(16) float g_xo    [(size_t)SEQ * DIM];

// ---------------------------------------------------------------------------
// Helpers
// ---------------------------------------------------------------------------
__device__ __forceinline__ uint32_t f2tf32(float x) {
    uint32_t r;
    asm("cvt.rna.tf32.f32 %0, %1;" : "=r"(r) : "f"(x));
    return r;
}

__device__ __forceinline__ void mma_tf32(float* c, const uint32_t* a, const uint32_t* b) {
    asm volatile(
        "mma.sync.aligned.m16n8k8.row.col.f32.tf32.tf32.f32 "
        "{%0,%1,%2,%3}, {%4,%5,%6,%7}, {%8,%9}, {%0,%1,%2,%3};"
        : "+f"(c[0]), "+f"(c[1]), "+f"(c[2]), "+f"(c[3])
        : "r"(a[0]), "r"(a[1]), "r"(a[2]), "r"(a[3]), "r"(b[0]), "r"(b[1]));
}

__device__ __forceinline__ void ldsm_x4(uint32_t* r, uint32_t addr) {
    asm volatile("ldmatrix.sync.aligned.m8n8.x4.shared.b16 {%0,%1,%2,%3}, [%4];"
                 : "=r"(r[0]), "=r"(r[1]), "=r"(r[2]), "=r"(r[3]) : "r"(addr));
}

__device__ __forceinline__ void cp_async16(uint32_t dst, const float* src) {
    asm volatile("cp.async.cg.shared.global [%0], [%1], 16;" :: "r"(dst), "l"(src));
}
__device__ __forceinline__ void cp_commit() { asm volatile("cp.async.commit_group;"); }
template<int N> __device__ __forceinline__ void cp_wait() {
    asm volatile("cp.async.wait_group %0;" :: "n"(N));
}

__device__ __forceinline__ float fast_exp(float x) {
    float t = fmaxf(x * 1.4426950408889634f, -126.0f);
    float z = t + 12582912.0f;
    int   zi = __float_as_int(z);
    float n = z - 12582912.0f;
    float f = t - n;
    float p = fmaf(f, 1.3333558e-3f, 9.6181291e-3f);
    p = fmaf(f, p, 5.5504109e-2f);
    p = fmaf(f, p, 2.4022651e-1f);
    p = fmaf(f, p, 6.9314718e-1f);
    p = fmaf(f, p, 1.0f);
    return __int_as_float((zi << 23) + 0x3F800000) * p;
}

// ---------------------------------------------------------------------------
// Prep kernels
// ---------------------------------------------------------------------------
__global__ void round_tf32_kernel(const float* __restrict__ in, float* __restrict__ out, int n4)
{
    int i = blockIdx.x * blockDim.x + threadIdx.x;
    if (i < n4) {
        float4 v = ((const float4*)in)[i];
        v.x = __uint_as_float(f2tf32(v.x));
        v.y = __uint_as_float(f2tf32(v.y));
        v.z = __uint_as_float(f2tf32(v.z));
        v.w = __uint_as_float(f2tf32(v.w));
        ((float4*)out)[i] = v;
    }
}

__global__ void transpose_round_kernel(const float* __restrict__ W, float* __restrict__ Wt,
                                       int K, int N)
{
    __shared__ float tile[32][33];
    const int n0 = blockIdx.x * 32;
    const int k0 = blockIdx.y * 32;
    const int tx = threadIdx.x, ty = threadIdx.y;
#pragma unroll
    for (int dy = ty; dy < 32; dy += 8)
        tile[dy][tx] = W[(size_t)(k0 + dy) * N + n0 + tx];
    __syncthreads();
#pragma unroll
    for (int dy = ty; dy < 32; dy += 8)
        Wt[(size_t)(n0 + dy) * K + k0 + tx] = __uint_as_float(f2tf32(tile[tx][dy]));
}

// ---------------------------------------------------------------------------
// TF32 GEMM: C[M,N] = A[M,K] @ Bt[N,K]^T. 128x128 tile, K-chunk 32, 8 warps,
// 3-STAGE cp.async pipeline with ONE barrier per iteration.
// Per iter: wait stage it (in-order groups) -> barrier (visibility + proves
// compute(it-1) done in all warps) -> issue stage it+2 into buf (it-1)%3
// (provably free) -> compute stage it. Prefetch window ~= 2 compute iters.
// ---------------------------------------------------------------------------
#define GKB 32
#define LDA 36                         // stride%32==4 -> conflict-free ldmatrix
#define GSTG 3
#define ABUF (128 * LDA)               // floats per A stage
#define GEMM_SMEM_BYTES ((2 * GSTG * ABUF) * 4)   // 110592 B

__global__ __launch_bounds__(256, 2)
void gemm_tf32(const float* __restrict__ A, const float* __restrict__ Bt,
               float* __restrict__ C, int N, int K, int round_out)
{
    extern __shared__ float gsm[];

    const int tid  = threadIdx.x;
    const int lane = tid & 31;
    const int wid  = tid >> 5;
    const int g    = lane >> 2;
    const int tig  = lane & 3;
    const int rowW = (wid & 1) * 64;
    const int colW = (wid >> 1) * 32;
    const int bm = blockIdx.y * 128;
    const int bn = blockIdx.x * 128;

    const int crow = tid >> 1, ccol = (tid & 1) * 16;

    const uint32_t smem_s = (uint32_t)__cvta_generic_to_shared(gsm);
    const uint32_t a_dst0 = smem_s + (uint32_t)(crow * LDA + ccol) * 4u;
    const uint32_t b_dst0 = smem_s + (uint32_t)(GSTG * ABUF + crow * LDA + ccol) * 4u;

    const float* Ag = A  + (size_t)(bm + crow) * K + ccol;
    const float* Bg = Bt + (size_t)(bn + crow) * K + ccol;

    const int arow_l = ((lane >> 3) & 1) * 8 + (lane & 7);
    const int acol_l = (lane >> 4) * 4;
    const int brow_l = (lane >> 4) * 8 + (lane & 7);
    const int bcol_l = ((lane >> 3) & 1) * 4;

    const uint32_t a_lm0 = smem_s + (uint32_t)((rowW + arow_l) * LDA + acol_l) * 4u;
    const uint32_t b_lm0 = smem_s + (uint32_t)(GSTG * ABUF + (colW + brow_l) * LDA + bcol_l) * 4u;

    float acc[16][4];
#pragma unroll
    for (int i = 0; i < 16; i++) { acc[i][0] = acc[i][1] = acc[i][2] = acc[i][3] = 0.f; }

    const int nIter = K / GKB;         // 64

#define GEMM_ISSUE(IT, BUF) do {                                              \
        int _k0 = (IT) * GKB;                                                 \
        uint32_t _ad = a_dst0 + (uint32_t)((BUF) * ABUF) * 4u;                \
        const float* _ap = Ag + _k0;                                          \
        _Pragma("unroll")                                                     \
        for (int _v = 0; _v < 4; _v++) cp_async16(_ad + _v * 16u, _ap + _v * 4); \
        uint32_t _bd = b_dst0 + (uint32_t)((BUF) * ABUF) * 4u;                \
        const float* _bp = Bg + _k0;                                          \
        _Pragma("unroll")                                                     \
        for (int _v = 0; _v < 4; _v++) cp_async16(_bd + _v * 16u, _bp + _v * 4); \
        cp_commit();                                                          \
    } while (0)

    GEMM_ISSUE(0, 0);
    GEMM_ISSUE(1, 1);

    int buf = 0;                       // stage it lives in buf = it % 3
    for (int it = 0; it < nIter; ++it) {
        if (it < nIter - 1) cp_wait<1>(); else cp_wait<0>();
        __syncthreads();

        if (it + 2 < nIter) {
            const int ibuf = (buf + 2 >= GSTG) ? buf - 1 : buf + 2;   // (it+2)%3
            GEMM_ISSUE(it + 2, ibuf);
        }

        const uint32_t a_lm = a_lm0 + (uint32_t)(buf * ABUF) * 4u;
        const uint32_t b_lm = b_lm0 + (uint32_t)(buf * ABUF) * 4u;

#pragma unroll
        for (int ks = 0; ks < GKB; ks += 8) {
            uint32_t af[4][4], bf[4][2];
#pragma unroll
            for (int mt = 0; mt < 4; mt++)
                ldsm_x4(af[mt], a_lm + (uint32_t)(mt * 16 * LDA + ks) * 4u);
#pragma unroll
            for (int nt2 = 0; nt2 < 2; nt2++) {
                uint32_t t[4];
                ldsm_x4(t, b_lm + (uint32_t)(nt2 * 16 * LDA + ks) * 4u);
                bf[2 * nt2][0]     = t[0];
                bf[2 * nt2][1]     = t[1];
                bf[2 * nt2 + 1][0] = t[2];
                bf[2 * nt2 + 1][1] = t[3];
            }
#pragma unroll
            for (int mt = 0; mt < 4; mt++)
#pragma unroll
                for (int nt = 0; nt < 4; nt++)
                    mma_tf32(acc[mt * 4 + nt], af[mt], bf[nt]);
        }

        buf = (buf + 1 == GSTG) ? 0 : buf + 1;
    }

#pragma unroll
    for (int mt = 0; mt < 4; mt++) {
        const int r0 = bm + rowW + mt * 16 + g;
#pragma unroll
        for (int nt = 0; nt < 4; nt++) {
            float v0 = acc[mt * 4 + nt][0], v1 = acc[mt * 4 + nt][1];
            float v2 = acc[mt * 4 + nt][2], v3 = acc[mt * 4 + nt][3];
            if (round_out) {
                v0 = __uint_as_float(f2tf32(v0));
                v1 = __uint_as_float(f2tf32(v1));
                v2 = __uint_as_float(f2tf32(v2));
                v3 = __uint_as_float(f2tf32(v3));
            }
            float* p0 = C + (size_t)r0 * N + bn + colW + nt * 8 + 2 * tig;
            p0[0] = v0;
            p0[1] = v1;
            float* p1 = p0 + (size_t)8 * N;
            p1[0] = v2;
            p1[1] = v3;
        }
    }
#undef GEMM_ISSUE
}

// ---------------------------------------------------------------------------
// Flash attention, tf32 mma.sync + ldmatrix, 512 threads (16 warps).
// Br=128, Bc=64, d=128. Warp grids 4x4: S tile 32x16, PV tile 32x32.
// K double-buffered cp.async, V single-buffer issued early.
// ---------------------------------------------------------------------------
#define BR  128
#define BC  64
#define NT  (SEQ / BC)
#define LDQ 132
#define LDK 132
#define LDV 136
#define LDP 68
#define OFF_Q  0
#define OFF_K0 (BR * LDQ)
#define OFF_K1 (OFF_K0 + BC * LDK)
#define OFF_V  (OFF_K1 + BC * LDK)
#define OFF_P  (OFF_V + BC * LDV)
#define OFF_M  (OFF_P + BR * LDP)
#define OFF_L  (OFF_M + BR)
#define OFF_CR (OFF_L + BR)
#define ATTN_SMEM_WORDS (OFF_CR + BR)
#define ATTN_SMEM_BYTES (ATTN_SMEM_WORDS * 4)

__global__ __launch_bounds__(512, 1)
void attn_tf32(const float* __restrict__ xqkv, float* __restrict__ xo)
{
    extern __shared__ float sm[];
    float* Ps     = sm + OFF_P;
    float* m_s    = sm + OFF_M;
    float* l_s    = sm + OFF_L;
    float* corr_s = sm + OFF_CR;

    const int tid  = threadIdx.x;
    const int lane = tid & 31;
    const int wid  = tid >> 5;              // 0..15
    const int g    = lane >> 2;
    const int tig  = lane & 3;
    const int wM   = wid & 3;               // 0..3 -> 32-row band
    const int wN   = wid >> 2;              // 0..3 -> 16-col (S) / 32-col (PV) band

    const int h  = blockIdx.y;
    const int q0 = blockIdx.x * BR;

    const float* Qg = xqkv + (size_t)q0 * QKV_N + h * HDIM;
    const float* Kg = xqkv + 2048 + h * HDIM;
    const float* Vg = xqkv + 4096 + h * HDIM;

    const uint32_t smem_b = (uint32_t)__cvta_generic_to_shared(sm);

    const int arow_l = ((lane >> 3) & 1) * 8 + (lane & 7);
    const int acol_l = (lane >> 4) * 4;
    const int brow_l = (lane >> 4) * 8 + (lane & 7);
    const int bcol_l = ((lane >> 3) & 1) * 4;

    const uint32_t q_lm = smem_b + (uint32_t)(OFF_Q + (32 * wM + arow_l) * LDQ + acol_l) * 4u;
    const uint32_t p_lm = smem_b + (uint32_t)(OFF_P + (32 * wM + arow_l) * LDP + acol_l) * 4u;
    const uint32_t k_lm_base = (uint32_t)((16 * wN + brow_l) * LDK + bcol_l) * 4u;

    // --- prologue: async-load Q tile + K(0) ---
    {
        const int row = tid >> 2, c0 = (tid & 3) * 32;   // Q: 128x128
        const uint32_t qd = smem_b + (uint32_t)(OFF_Q + row * LDQ + c0) * 4u;
        const float* qs = Qg + (size_t)row * QKV_N + c0;
#pragma unroll
        for (int j = 0; j < 8; j++) cp_async16(qd + j * 16u, qs + j * 4);

        const int kr = tid >> 3, kc = (tid & 7) * 16;    // K: 64x128
        const uint32_t kd = smem_b + (uint32_t)(OFF_K0 + kr * LDK + kc) * 4u;
        const float* ks = Kg + (size_t)kr * QKV_N + kc;
#pragma unroll
        for (int j = 0; j < 4; j++) cp_async16(kd + j * 16u, ks + j * 4);
        cp_commit();
    }
    if (tid < BR) { m_s[tid] = -INFINITY; l_s[tid] = 0.f; }

    float oacc[8][4];
#pragma unroll
    for (int i = 0; i < 8; i++) { oacc[i][0] = oacc[i][1] = oacc[i][2] = oacc[i][3] = 0.f; }

    const float scale = 0.08838834764831845f;
    const int krow = tid >> 3, kc0 = (tid & 7) * 16;

    for (int t = 0; t < NT; ++t) {
        const int b = t & 1;
        __syncthreads();   // V buf free (PV(t-1) done); covers stats init on t=0

        // issue V(t) and K(t+1) as one commit group
        {
            const uint32_t vd = smem_b + (uint32_t)(OFF_V + krow * LDV + kc0) * 4u;
            const float* vs = Vg + (size_t)(t * BC + krow) * QKV_N + kc0;
#pragma unroll
            for (int j = 0; j < 4; j++) cp_async16(vd + j * 16u, vs + j * 4);
            if (t + 1 < NT) {
                const int koff = (b ? OFF_K0 : OFF_K1);
                const uint32_t kd = smem_b + (uint32_t)(koff + krow * LDK + kc0) * 4u;
                const float* ks = Kg + (size_t)((t + 1) * BC + krow) * QKV_N + kc0;
#pragma unroll
                for (int j = 0; j < 4; j++) cp_async16(kd + j * 16u, ks + j * 4);
            }
            cp_commit();
        }

        cp_wait<1>();      // previous group done -> K(t) (and Q on t=0) resident
        __syncthreads();

        const uint32_t k_lm = smem_b + (uint32_t)(b ? OFF_K1 : OFF_K0) * 4u + k_lm_base;

        // ---- S phase: S[128x64] = Q @ K^T, warp tile 32x16 ----
        float sacc[4][4];
#pragma unroll
        for (int i = 0; i < 4; i++) { sacc[i][0] = sacc[i][1] = sacc[i][2] = sacc[i][3] = 0.f; }

#pragma unroll
        for (int kk = 0; kk < HDIM; kk += 8) {
            uint32_t af[2][4], bf[2][2];
#pragma unroll
            for (int mt = 0; mt < 2; mt++)
                ldsm_x4(af[mt], q_lm + (uint32_t)(mt * 16 * LDQ + kk) * 4u);
            {
                uint32_t tr[4];
                ldsm_x4(tr, k_lm + (uint32_t)kk * 4u);
                bf[0][0] = tr[0]; bf[0][1] = tr[1];
                bf[1][0] = tr[2]; bf[1][1] = tr[3];
            }
#pragma unroll
            for (int mt = 0; mt < 2; mt++)
#pragma unroll
                for (int nt = 0; nt < 2; nt++)
                    mma_tf32(sacc[mt * 2 + nt], af[mt], bf[nt]);
        }

        // write raw scores
#pragma unroll
        for (int mt = 0; mt < 2; mt++)
#pragma unroll
            for (int nt = 0; nt < 2; nt++) {
                const int row = 32 * wM + mt * 16 + g;
                const int col = 16 * wN + nt * 8 + 2 * tig;
                float* p = Ps + row * LDP + col;
                p[0] = sacc[mt * 2 + nt][0];
                p[1] = sacc[mt * 2 + nt][1];
                float* q = p + 8 * LDP;
                q[0] = sacc[mt * 2 + nt][2];
                q[1] = sacc[mt * 2 + nt][3];
            }
        __syncthreads();

        // ---- softmax: 4 threads per row, 16 cols each ----
        {
            const int r = tid >> 2, c0 = (tid & 3) * 16;
            float* prow = Ps + r * LDP + c0;
            float v[16];
#pragma unroll
            for (int j = 0; j < 16; j += 4) {
                float4 x = *(const float4*)(prow + j);
                v[j] = x.x; v[j + 1] = x.y; v[j + 2] = x.z; v[j + 3] = x.w;
            }
            const float mold = m_s[r];
            float tmax = -INFINITY;
#pragma unroll
            for (int j = 0; j < 16; j++) { v[j] *= scale; tmax = fmaxf(tmax, v[j]); }
            tmax = fmaxf(tmax, __shfl_xor_sync(0xffffffffu, tmax, 1));
            tmax = fmaxf(tmax, __shfl_xor_sync(0xffffffffu, tmax, 2));
            const float mnew = fmaxf(mold, tmax);
            const float corr = fast_exp(mold - mnew);
            float lsum = 0.f;
#pragma unroll
            for (int j = 0; j < 16; j++) { v[j] = fast_exp(v[j] - mnew); lsum += v[j]; }
#pragma unroll
            for (int j = 0; j < 16; j += 4) {
                float4 x = { __uint_as_float(f2tf32(v[j])),     __uint_as_float(f2tf32(v[j + 1])),
                             __uint_as_float(f2tf32(v[j + 2])), __uint_as_float(f2tf32(v[j + 3])) };
                *(float4*)(prow + j) = x;
            }
            lsum += __shfl_xor_sync(0xffffffffu, lsum, 1);
            lsum += __shfl_xor_sync(0xffffffffu, lsum, 2);
            if ((tid & 3) == 0) {
                m_s[r] = mnew;
                l_s[r] = l_s[r] * corr + lsum;
                corr_s[r] = corr;
            }
        }

        cp_wait<0>();      // this iter's group done -> V(t) resident
        __syncthreads();   // + P, stats visible

        const float* Vs = sm + OFF_V;

        // ---- PV phase: O[128x128] += P @ V, warp tile 32x32 ----
        float c0m[2], c1m[2];
#pragma unroll
        for (int mt = 0; mt < 2; mt++) {
            c0m[mt] = corr_s[32 * wM + mt * 16 + g];
            c1m[mt] = corr_s[32 * wM + mt * 16 + g + 8];
        }
#pragma unroll
        for (int mt = 0; mt < 2; mt++)
#pragma unroll
            for (int nt = 0; nt < 4; nt++) {
                float* a = oacc[mt * 4 + nt];
                a[0] *= c0m[mt]; a[1] *= c0m[mt];
                a[2] *= c1m[mt]; a[3] *= c1m[mt];
            }

#pragma unroll
        for (int kk = 0; kk < BC; kk += 8) {
            uint32_t af[2][4], bf[4][2];
#pragma unroll
            for (int mt = 0; mt < 2; mt++)
                ldsm_x4(af[mt], p_lm + (uint32_t)(mt * 16 * LDP + kk) * 4u);
#pragma unroll
            for (int nt = 0; nt < 4; nt++) {
                const float* bp = Vs + (kk + tig) * LDV + 32 * wN + nt * 8 + g;
                bf[nt][0] = __float_as_uint(bp[0]);
                bf[nt][1] = __float_as_uint(bp[4 * LDV]);
            }
#pragma unroll
            for (int mt = 0; mt < 2; mt++)
#pragma unroll
                for (int nt = 0; nt < 4; nt++)
                    mma_tf32(oacc[mt * 4 + nt], af[mt], bf[nt]);
        }
    }

    // ---- normalize + write O (tf32-rounded: GEMM2's A operand) ----
#pragma unroll
    for (int mt = 0; mt < 2; mt++) {
        const int row = 32 * wM + mt * 16 + g;
        const float il0 = 1.f / l_s[row];
        const float il1 = 1.f / l_s[row + 8];
        float* out0 = xo + (size_t)(q0 + row) * DIM + h * HDIM + 32 * wN;
        float* out1 = out0 + (size_t)8 * DIM;
#pragma unroll
        for (int nt = 0; nt < 4; nt++) {
            const int c = nt * 8 + 2 * tig;
            out0[c]     = __uint_as_float(f2tf32(oacc[mt * 4 + nt][0] * il0));
            out0[c + 1] = __uint_as_float(f2tf32(oacc[mt * 4 + nt][1] * il0));
            out1[c]     = __uint_as_float(f2tf32(oacc[mt * 4 + nt][2] * il1));
            out1[c + 1] = __uint_as_float(f2tf32(oacc[mt * 4 + nt][3] * il1));
        }
    }
}

// ---------------------------------------------------------------------------
// Launch
// ---------------------------------------------------------------------------
extern "C" void kernel_launch(void* const* d_in, const int* in_sizes, int n_in,
                              void* d_out, int out_size)
{
    const float* x    = (const float*)d_in[0];
    const float* Wqkv = (const float*)d_in[1];
    const float* Wo   = (const float*)d_in[2];
    float* out = (float*)d_out;

    float *xr, *wqkvT, *woT, *xqkv, *xo;
    cudaGetSymbolAddress((void**)&xr,    g_xr);
    cudaGetSymbolAddress((void**)&wqkvT, g_wqkvT);
    cudaGetSymbolAddress((void**)&woT,   g_woT);
    cudaGetSymbolAddress((void**)&xqkv,  g_xqkv);
    cudaGetSymbolAddress((void**)&xo,    g_xo);

    cudaFuncSetAttribute(gemm_tf32, cudaFuncAttributeMaxDynamicSharedMemorySize,
                         GEMM_SMEM_BYTES);
    cudaFuncSetAttribute(attn_tf32, cudaFuncAttributeMaxDynamicSharedMemorySize,
                         ATTN_SMEM_BYTES);

    // 0) prep
    round_tf32_kernel<<<(SEQ * DIM / 4) / 256, 256>>>(x, xr, SEQ * DIM / 4);
    {
        dim3 blk(32, 8);
        transpose_round_kernel<<<dim3(QKV_N / 32, DIM / 32), blk>>>(Wqkv, wqkvT, DIM, QKV_N);
        transpose_round_kernel<<<dim3(DIM / 32, DIM / 32),  blk>>>(Wo,   woT,   DIM, DIM);
    }
    // 1) xqkv = x @ Wqkv
    {
        dim3 grid(QKV_N / 128, SEQ / 128);
        gemm_tf32<<<grid, 256, GEMM_SMEM_BYTES>>>(xr, wqkvT, xqkv, QKV_N, DIM, 1);
    }
    // 2) flash attention -> xo
    {
        dim3 grid(SEQ / BR, NHEADS);
        attn_tf32<<<grid, 512, ATTN_SMEM_BYTES>>>(xqkv, xo);
    }
    // 3) out = xo @ Wo
    {
        dim3 grid(DIM / 128, SEQ / 128);
        gemm_tf32<<<grid, 256, GEMM_SMEM_BYTES>>>(xo, woT, out, DIM, DIM, 0);
    }
}

// round 7
// speedup vs baseline: 1.6979x; 1.6979x over previous
#include <cuda_runtime.h>
#include <cuda_fp16.h>
#include <cstdint>
#include <math.h>

// ---------------------------------------------------------------------------
// Problem constants
// ---------------------------------------------------------------------------
#define SEQ     4096
#define DIM     2048
#define NHEADS  16
#define HDIM    128
#define QKV_N   6144

// ---------------------------------------------------------------------------
// Scratch (device globals; allocation forbidden)
// ---------------------------------------------------------------------------
__device__ __align__(16) __half g_xh   [(size_t)SEQ * DIM];     // x  fp16
__device__ __align__(16) __half g_wqkvT[(size_t)QKV_N * DIM];   // Wqkv^T fp16 (Q-third pre-scaled by 1/sqrt(d))
__device__ __align__(16) __half g_woT  [(size_t)DIM * DIM];     // Wo^T fp16
__device__ __align__(16) __half g_xqkv [(size_t)SEQ * QKV_N];   // GEMM1 out fp16
__device__ __align__(16) __half g_xo   [(size_t)SEQ * DIM];     // attn out fp16

// ---------------------------------------------------------------------------
// Helpers
// ---------------------------------------------------------------------------
__device__ __forceinline__ void mma_f16(float* c, const uint32_t* a, const uint32_t* b) {
    asm volatile(
        "mma.sync.aligned.m16n8k16.row.col.f32.f16.f16.f32 "
        "{%0,%1,%2,%3}, {%4,%5,%6,%7}, {%8,%9}, {%0,%1,%2,%3};"
        : "+f"(c[0]), "+f"(c[1]), "+f"(c[2]), "+f"(c[3])
        : "r"(a[0]), "r"(a[1]), "r"(a[2]), "r"(a[3]), "r"(b[0]), "r"(b[1]));
}

__device__ __forceinline__ void ldsm_x4(uint32_t* r, uint32_t addr) {
    asm volatile("ldmatrix.sync.aligned.m8n8.x4.shared.b16 {%0,%1,%2,%3}, [%4];"
                 : "=r"(r[0]), "=r"(r[1]), "=r"(r[2]), "=r"(r[3]) : "r"(addr));
}
__device__ __forceinline__ void ldsm_x4_t(uint32_t* r, uint32_t addr) {
    asm volatile("ldmatrix.sync.aligned.m8n8.x4.trans.shared.b16 {%0,%1,%2,%3}, [%4];"
                 : "=r"(r[0]), "=r"(r[1]), "=r"(r[2]), "=r"(r[3]) : "r"(addr));
}

__device__ __forceinline__ void cp_async16(uint32_t dst, const void* src) {
    asm volatile("cp.async.cg.shared.global [%0], [%1], 16;" :: "r"(dst), "l"(src));
}
__device__ __forceinline__ void cp_commit() { asm volatile("cp.async.commit_group;"); }
template<int N> __device__ __forceinline__ void cp_wait() {
    asm volatile("cp.async.wait_group %0;" :: "n"(N));
}

// FMA-only exp, valid for x <= 0. Keeps the MUFU pipe idle (335M exps total).
__device__ __forceinline__ float fast_exp(float x) {
    float t = fmaxf(x * 1.4426950408889634f, -126.0f);
    float z = t + 12582912.0f;
    int   zi = __float_as_int(z);
    float n = z - 12582912.0f;
    float f = t - n;
    float p = fmaf(f, 1.3333558e-3f, 9.6181291e-3f);
    p = fmaf(f, p, 5.5504109e-2f);
    p = fmaf(f, p, 2.4022651e-1f);
    p = fmaf(f, p, 6.9314718e-1f);
    p = fmaf(f, p, 1.0f);
    return __int_as_float((zi << 23) + 0x3F800000) * p;
}

// ---------------------------------------------------------------------------
// Prep kernels
// ---------------------------------------------------------------------------
__global__ void f2h_kernel(const float* __restrict__ in, __half* __restrict__ out, int n4)
{
    int i = blockIdx.x * blockDim.x + threadIdx.x;
    if (i < n4) {
        float4 v = ((const float4*)in)[i];
        __half2* o = (__half2*)out + 2 * (size_t)i;
        o[0] = __floats2half2_rn(v.x, v.y);
        o[1] = __floats2half2_rn(v.z, v.w);
    }
}

// Wt[n][k] = fp16(W[k][n] * (n < scaleLimit ? scale : 1)); W is [K,N] row-major.
__global__ void transpose_h_kernel(const float* __restrict__ W, __half* __restrict__ Wt,
                                   int K, int N, int scaleLimit, float scale)
{
    __shared__ float tile[32][33];
    const int n0 = blockIdx.x * 32;
    const int k0 = blockIdx.y * 32;
    const int tx = threadIdx.x, ty = threadIdx.y;
#pragma unroll
    for (int dy = ty; dy < 32; dy += 8)
        tile[dy][tx] = W[(size_t)(k0 + dy) * N + n0 + tx];
    __syncthreads();
#pragma unroll
    for (int dy = ty; dy < 32; dy += 8) {
        int n = n0 + dy;
        float s = (n < scaleLimit) ? scale : 1.0f;
        Wt[(size_t)n * K + k0 + tx] = __float2half_rn(tile[tx][dy] * s);
    }
}

// ---------------------------------------------------------------------------
// FP16 GEMM: C[M,N] = A[M,K] @ Bt[N,K]^T, fp32 accumulate.
// CTA 128x128, K-chunk 64 halves, 8 warps (warp tile 64x32), 3-stage cp.async.
// smem rows padded to 72 halves (144B, ==16 mod 32B -> conflict-free ldmatrix).
// ---------------------------------------------------------------------------
#define GKH 64
#define LDH 72
#define GSTG_B 36864                        // bytes per stage (256 rows * 144B)
#define GEMM_SMEM_BYTES (3 * GSTG_B)        // 110592

__global__ __launch_bounds__(256, 2)
void gemm_f16(const __half* __restrict__ A, const __half* __restrict__ Bt,
              void* __restrict__ Cv, int N, int K, int out_half)
{
    extern __shared__ char smc[];
    const uint32_t sb = (uint32_t)__cvta_generic_to_shared(smc);

    const int tid  = threadIdx.x;
    const int lane = tid & 31;
    const int wid  = tid >> 5;
    const int g    = lane >> 2;
    const int tig  = lane & 3;
    const int rowW = (wid & 1) * 64;
    const int colW = (wid >> 1) * 32;
    const int bm = blockIdx.y * 128;
    const int bn = blockIdx.x * 128;

    // cp.async: thread owns one smem row (A: rows 0-127, B: rows 128-255)
    const __half* grow = (tid < 128) ? (A + (size_t)(bm + tid) * K)
                                     : (Bt + (size_t)(bn + tid - 128) * K);
    const uint32_t drow = sb + (uint32_t)tid * 144u;

    // ldmatrix lane parts
    const int arow_l = (lane & 7) + ((lane >> 3) & 1) * 8;
    const uint32_t lpA = (uint32_t)arow_l * 144u + (uint32_t)(lane >> 4) * 16u;
    const int brow_l = (lane >> 4) * 8 + (lane & 7);
    const uint32_t lpB = (uint32_t)brow_l * 144u + (uint32_t)((lane >> 3) & 1) * 16u;

    const uint32_t aBase0 = sb + (uint32_t)rowW * 144u + lpA;
    const uint32_t bBase0 = sb + (uint32_t)(128 + colW) * 144u + lpB;

    float acc[16][4];
#pragma unroll
    for (int i = 0; i < 16; i++) { acc[i][0] = acc[i][1] = acc[i][2] = acc[i][3] = 0.f; }

    const int nIter = K / GKH;              // 32

#define GEMM_ISSUE(IT, BUF) do {                                               \
        const __half* _gp = grow + (IT) * GKH;                                 \
        uint32_t _d = drow + (uint32_t)((BUF) * GSTG_B);                       \
        _Pragma("unroll")                                                      \
        for (int _j = 0; _j < 8; _j++) cp_async16(_d + _j * 16u, _gp + _j * 8);\
        cp_commit();                                                           \
    } while (0)

    GEMM_ISSUE(0, 0);
    GEMM_ISSUE(1, 1);

    int buf = 0;
    for (int it = 0; it < nIter; ++it) {
        if (it < nIter - 1) cp_wait<1>(); else cp_wait<0>();
        __syncthreads();

        if (it + 2 < nIter) {
            const int ibuf = (buf + 2 >= 3) ? buf - 1 : buf + 2;
            GEMM_ISSUE(it + 2, ibuf);
        }

        const uint32_t aB = aBase0 + (uint32_t)(buf * GSTG_B);
        const uint32_t bB = bBase0 + (uint32_t)(buf * GSTG_B);

#pragma unroll
        for (int ks = 0; ks < 4; ks++) {            // 4 x k16
            uint32_t af[4][4], bf[4][2];
#pragma unroll
            for (int mt = 0; mt < 4; mt++)
                ldsm_x4(af[mt], aB + (uint32_t)(mt * 16 * 144 + ks * 32));
#pragma unroll
            for (int ng = 0; ng < 2; ng++) {
                uint32_t t4[4];
                ldsm_x4(t4, bB + (uint32_t)(ng * 16 * 144 + ks * 32));
                bf[2 * ng][0]     = t4[0];
                bf[2 * ng][1]     = t4[1];
                bf[2 * ng + 1][0] = t4[2];
                bf[2 * ng + 1][1] = t4[3];
            }
#pragma unroll
            for (int mt = 0; mt < 4; mt++)
#pragma unroll
                for (int nt = 0; nt < 4; nt++)
                    mma_f16(acc[mt * 4 + nt], af[mt], bf[nt]);
        }
        buf = (buf + 1 == 3) ? 0 : buf + 1;
    }

    if (out_half) {
        __half* C = (__half*)Cv;
#pragma unroll
        for (int mt = 0; mt < 4; mt++) {
            const int r0 = bm + rowW + mt * 16 + g;
#pragma unroll
            for (int nt = 0; nt < 4; nt++) {
                const int col = bn + colW + nt * 8 + 2 * tig;
                *(__half2*)(C + (size_t)r0 * N + col) =
                    __floats2half2_rn(acc[mt * 4 + nt][0], acc[mt * 4 + nt][1]);
                *(__half2*)(C + (size_t)(r0 + 8) * N + col) =
                    __floats2half2_rn(acc[mt * 4 + nt][2], acc[mt * 4 + nt][3]);
            }
        }
    } else {
        float* C = (float*)Cv;
#pragma unroll
        for (int mt = 0; mt < 4; mt++) {
            const int r0 = bm + rowW + mt * 16 + g;
#pragma unroll
            for (int nt = 0; nt < 4; nt++) {
                const int col = bn + colW + nt * 8 + 2 * tig;
                *(float2*)(C + (size_t)r0 * N + col) =
                    make_float2(acc[mt * 4 + nt][0], acc[mt * 4 + nt][1]);
                *(float2*)(C + (size_t)(r0 + 8) * N + col) =
                    make_float2(acc[mt * 4 + nt][2], acc[mt * 4 + nt][3]);
            }
        }
    }
#undef GEMM_ISSUE
}

// ---------------------------------------------------------------------------
// FP16 flash attention. Br=Bc=64, d=128, 256 threads (8 warps), 2 CTAs/SM.
// S warp grid 2x4 (tile 32x16), PV 2x4 (tile 32x32). Softmax in registers
// (cross-warp row stats via pmax/psum smem). 1/sqrt(d) pre-folded into Wq.
// ---------------------------------------------------------------------------
#define BR 64
#define BC 64
#define NT (SEQ / BC)        // 64
// byte offsets (rows padded to 136 halves = 272B; P rows 72 halves = 144B)
#define AQ   0
#define AK0  17408
#define AK1  34816
#define AV   52224
#define AP   69632
#define APM  78848           // pmax [4][64] float
#define APS  79872           // psum [4][64] float
#define AMS  80896           // m_s  [2][64] float
#define ALS  81408           // l_s  [2][64] float
#define ATTN_SMEM_BYTES 81920

__global__ __launch_bounds__(256, 2)
void attn_f16(const __half* __restrict__ xqkv, __half* __restrict__ xo)
{
    extern __shared__ char smc[];
    const uint32_t sb = (uint32_t)__cvta_generic_to_shared(smc);
    float* pmax = (float*)(smc + APM);
    float* psum = (float*)(smc + APS);
    float* m_s  = (float*)(smc + AMS);
    float* l_s  = (float*)(smc + ALS);

    const int tid  = threadIdx.x;
    const int lane = tid & 31;
    const int wid  = tid >> 5;
    const int g    = lane >> 2;
    const int tig  = lane & 3;
    const int wM   = wid & 1;            // 0..1 -> 32-row band
    const int wN   = wid >> 1;           // 0..3 -> 16-col (S) / 32-col (PV) band

    const int h  = blockIdx.y;
    const int q0 = blockIdx.x * BR;

    const __half* Qg = xqkv + (size_t)q0 * QKV_N + h * HDIM;
    const __half* Kg = xqkv + 2048 + h * HDIM;
    const __half* Vg = xqkv + 4096 + h * HDIM;

    // cp.async mapping: row = tid>>2 (0..63), byte off = (tid&3)*64 + j*16
    const int crow = tid >> 2;
    const int cbo  = (tid & 3) * 64;     // bytes; halves offset = cbo/2

    // ldmatrix lane parts
    const int arow_l = (lane & 7) + ((lane >> 3) & 1) * 8;
    const uint32_t lpA272 = (uint32_t)arow_l * 272u + (uint32_t)(lane >> 4) * 16u;
    const uint32_t lpA144 = (uint32_t)arow_l * 144u + (uint32_t)(lane >> 4) * 16u;
    const int brow_l = (lane >> 4) * 8 + (lane & 7);
    const uint32_t lpB272 = (uint32_t)brow_l * 272u + (uint32_t)((lane >> 3) & 1) * 16u;

    const uint32_t q_lm   = sb + AQ + (uint32_t)(32 * wM) * 272u + lpA272;
    const uint32_t k_lmBo = (uint32_t)(16 * wN) * 272u + lpB272;
    const uint32_t p_lm   = sb + AP + (uint32_t)(32 * wM) * 144u + lpA144;
    const uint32_t v_lm   = sb + AV + lpA272;

    // --- prologue: Q + K(0) in one group ---
    {
        const __half* qs = Qg + (size_t)crow * QKV_N + cbo / 2;
        const __half* ks = Kg + (size_t)crow * QKV_N + cbo / 2;
        const uint32_t qd = sb + AQ  + (uint32_t)crow * 272u + cbo;
        const uint32_t kd = sb + AK0 + (uint32_t)crow * 272u + cbo;
#pragma unroll
        for (int j = 0; j < 4; j++) { cp_async16(qd + j * 16u, qs + j * 8); }
#pragma unroll
        for (int j = 0; j < 4; j++) { cp_async16(kd + j * 16u, ks + j * 8); }
        cp_commit();
    }
    if (tid < BR) { m_s[tid] = -INFINITY; l_s[tid] = 0.f; }   // slot 0

    float oacc[8][4];
#pragma unroll
    for (int i = 0; i < 8; i++) { oacc[i][0] = oacc[i][1] = oacc[i][2] = oacc[i][3] = 0.f; }

    for (int t = 0; t < NT; ++t) {
        const int cur = t & 1, nxt = cur ^ 1;
        __syncthreads();                 // V buffer free; stats init on t=0

        // issue V(t) and K(t+1) as one group
        {
            const __half* vs = Vg + (size_t)(t * BC + crow) * QKV_N + cbo / 2;
            const uint32_t vd = sb + AV + (uint32_t)crow * 272u + cbo;
#pragma unroll
            for (int j = 0; j < 4; j++) cp_async16(vd + j * 16u, vs + j * 8);
            if (t + 1 < NT) {
                const int koff = (cur == 0) ? AK1 : AK0;
                const __half* ks = Kg + (size_t)((t + 1) * BC + crow) * QKV_N + cbo / 2;
                const uint32_t kd = sb + koff + (uint32_t)crow * 272u + cbo;
#pragma unroll
                for (int j = 0; j < 4; j++) cp_async16(kd + j * 16u, ks + j * 8);
            }
            cp_commit();
        }

        cp_wait<1>();                    // K(t) (and Q on t=0) resident
        __syncthreads();

        const uint32_t k_lm = sb + ((cur == 0) ? AK0 : AK1) + k_lmBo;

        // ---- S phase: S[64x64] = Q @ K^T, warp tile 32x16 ----
        float sacc[4][4];
#pragma unroll
        for (int i = 0; i < 4; i++) { sacc[i][0] = sacc[i][1] = sacc[i][2] = sacc[i][3] = 0.f; }

#pragma unroll
        for (int ks = 0; ks < 8; ks++) {             // 8 x k16 over d=128
            uint32_t af[2][4], bf[2][2];
#pragma unroll
            for (int mt = 0; mt < 2; mt++)
                ldsm_x4(af[mt], q_lm + (uint32_t)(mt * 16 * 272 + ks * 32));
            {
                uint32_t t4[4];
                ldsm_x4(t4, k_lm + (uint32_t)(ks * 32));
                bf[0][0] = t4[0]; bf[0][1] = t4[1];
                bf[1][0] = t4[2]; bf[1][1] = t4[3];
            }
#pragma unroll
            for (int mt = 0; mt < 2; mt++)
#pragma unroll
                for (int nt = 0; nt < 2; nt++)
                    mma_f16(sacc[mt * 2 + nt], af[mt], bf[nt]);
        }

        // ---- softmax in registers ----
        // rows: r(mt,hh) = 32*wM + 16*mt + g + 8*hh
        // row (mt,hh) vals = sacc[2mt][2hh], sacc[2mt][2hh+1], sacc[2mt+1][2hh], sacc[2mt+1][2hh+1]
#pragma unroll
        for (int mt = 0; mt < 2; mt++)
#pragma unroll
            for (int hh = 0; hh < 2; hh++) {
                float a0 = sacc[2 * mt][2 * hh],     a1 = sacc[2 * mt][2 * hh + 1];
                float a2 = sacc[2 * mt + 1][2 * hh], a3 = sacc[2 * mt + 1][2 * hh + 1];
                float mx = fmaxf(fmaxf(a0, a1), fmaxf(a2, a3));
                mx = fmaxf(mx, __shfl_xor_sync(0xffffffffu, mx, 1));
                mx = fmaxf(mx, __shfl_xor_sync(0xffffffffu, mx, 2));
                if (tig == 0) pmax[wN * 64 + 32 * wM + 16 * mt + g + 8 * hh] = mx;
            }
        __syncthreads();                 // barrier 1: pmax ready

        float corr[2][2];
#pragma unroll
        for (int mt = 0; mt < 2; mt++)
#pragma unroll
            for (int hh = 0; hh < 2; hh++) {
                const int r = 32 * wM + 16 * mt + g + 8 * hh;
                const float mold = m_s[cur * 64 + r];
                float mn = fmaxf(fmaxf(pmax[r], pmax[64 + r]),
                                 fmaxf(pmax[128 + r], pmax[192 + r]));
                mn = fmaxf(mold, mn);
                const float co = fast_exp(mold - mn);
                corr[mt][hh] = co;
                if (wN == 0 && tig == 0) m_s[nxt * 64 + r] = mn;

                float e0 = fast_exp(sacc[2 * mt][2 * hh] - mn);
                float e1 = fast_exp(sacc[2 * mt][2 * hh + 1] - mn);
                float e2 = fast_exp(sacc[2 * mt + 1][2 * hh] - mn);
                float e3 = fast_exp(sacc[2 * mt + 1][2 * hh + 1] - mn);
                float sum = (e0 + e1) + (e2 + e3);
                sum += __shfl_xor_sync(0xffffffffu, sum, 1);
                sum += __shfl_xor_sync(0xffffffffu, sum, 2);
                if (tig == 0) psum[wN * 64 + r] = sum;

                // store P fp16 (cols 16wN+2tig / +8+2tig)
                char* pr = smc + AP + (size_t)r * 144;
                *(__half2*)(pr + (16 * wN + 2 * tig) * 2)     = __floats2half2_rn(e0, e1);
                *(__half2*)(pr + (16 * wN + 8 + 2 * tig) * 2) = __floats2half2_rn(e2, e3);
            }

        cp_wait<0>();                    // V(t) resident
        __syncthreads();                 // barrier 2: P, psum, V visible

        if (wN == 0 && tig == 0) {
#pragma unroll
            for (int mt = 0; mt < 2; mt++)
#pragma unroll
                for (int hh = 0; hh < 2; hh++) {
                    const int r = 32 * wM + 16 * mt + g + 8 * hh;
                    l_s[nxt * 64 + r] = l_s[cur * 64 + r] * corr[mt][hh] +
                        ((psum[r] + psum[64 + r]) + (psum[128 + r] + psum[192 + r]));
                }
        }

        // ---- PV: O[64x128] += P @ V, warp tile 32x32 ----
#pragma unroll
        for (int mt = 0; mt < 2; mt++)
#pragma unroll
            for (int nt = 0; nt < 4; nt++) {
                float* a = oacc[mt * 4 + nt];
                a[0] *= corr[mt][0]; a[1] *= corr[mt][0];
                a[2] *= corr[mt][1]; a[3] *= corr[mt][1];
            }

#pragma unroll
        for (int ks = 0; ks < 4; ks++) {             // 4 x k16 over Bc=64
            uint32_t paf[2][4], vbf[4][2];
#pragma unroll
            for (int mt = 0; mt < 2; mt++)
                ldsm_x4(paf[mt], p_lm + (uint32_t)(mt * 16 * 144 + ks * 32));
#pragma unroll
            for (int ng = 0; ng < 2; ng++) {
                uint32_t t4[4];
                ldsm_x4_t(t4, v_lm + (uint32_t)(ks * 16 * 272 + (32 * wN + ng * 16) * 2));
                vbf[2 * ng][0]     = t4[0];
                vbf[2 * ng][1]     = t4[1];
                vbf[2 * ng + 1][0] = t4[2];
                vbf[2 * ng + 1][1] = t4[3];
            }
#pragma unroll
            for (int mt = 0; mt < 2; mt++)
#pragma unroll
                for (int nt = 0; nt < 4; nt++)
                    mma_f16(oacc[mt * 4 + nt], paf[mt], vbf[nt]);
        }
    }

    // ---- epilogue: normalize, write fp16 xo ----
    __syncthreads();                     // last l_s writes visible
    const int fin = NT & 1;              // final slot parity (NT even -> 0)
#pragma unroll
    for (int mt = 0; mt < 2; mt++) {
        const int r0 = 32 * wM + 16 * mt + g;
        const float il0 = 1.f / l_s[fin * 64 + r0];
        const float il1 = 1.f / l_s[fin * 64 + r0 + 8];
#pragma unroll
        for (int nt = 0; nt < 4; nt++) {
            const int col = h * HDIM + 32 * wN + 8 * nt + 2 * tig;
            *(__half2*)(xo + (size_t)(q0 + r0) * DIM + col) =
                __floats2half2_rn(oacc[mt * 4 + nt][0] * il0, oacc[mt * 4 + nt][1] * il0);
            *(__half2*)(xo + (size_t)(q0 + r0 + 8) * DIM + col) =
                __floats2half2_rn(oacc[mt * 4 + nt][2] * il1, oacc[mt * 4 + nt][3] * il1);
        }
    }
}

// ---------------------------------------------------------------------------
// Launch
// ---------------------------------------------------------------------------
extern "C" void kernel_launch(void* const* d_in, const int* in_sizes, int n_in,
                              void* d_out, int out_size)
{
    const float* x    = (const float*)d_in[0];   // [4096, 2048]
    const float* Wqkv = (const float*)d_in[1];   // [2048, 6144]
    const float* Wo   = (const float*)d_in[2];   // [2048, 2048]
    float* out = (float*)d_out;                  // [4096, 2048]

    __half *xh, *wqkvT, *woT, *xqkv, *xo;
    cudaGetSymbolAddress((void**)&xh,    g_xh);
    cudaGetSymbolAddress((void**)&wqkvT, g_wqkvT);
    cudaGetSymbolAddress((void**)&woT,   g_woT);
    cudaGetSymbolAddress((void**)&xqkv,  g_xqkv);
    cudaGetSymbolAddress((void**)&xo,    g_xo);

    cudaFuncSetAttribute(gemm_f16, cudaFuncAttributeMaxDynamicSharedMemorySize,
                         GEMM_SMEM_BYTES);
    cudaFuncSetAttribute(attn_f16, cudaFuncAttributeMaxDynamicSharedMemorySize,
                         ATTN_SMEM_BYTES);

    // 0) prep: x -> fp16; Wqkv^T fp16 (Q-third scaled by 1/sqrt(d)); Wo^T fp16
    f2h_kernel<<<(SEQ * DIM / 4) / 256, 256>>>(x, xh, SEQ * DIM / 4);
    {
        dim3 blk(32, 8);
        transpose_h_kernel<<<dim3(QKV_N / 32, DIM / 32), blk>>>(
            Wqkv, wqkvT, DIM, QKV_N, NHEADS * HDIM, 0.08838834764831845f);
        transpose_h_kernel<<<dim3(DIM / 32, DIM / 32), blk>>>(
            Wo, woT, DIM, DIM, 0, 1.0f);
    }
    // 1) xqkv = x @ Wqkv  (fp16 out)
    {
        dim3 grid(QKV_N / 128, SEQ / 128);
        gemm_f16<<<grid, 256, GEMM_SMEM_BYTES>>>(xh, wqkvT, xqkv, QKV_N, DIM, 1);
    }
    // 2) flash attention -> xo (fp16)
    {
        dim3 grid(SEQ / BR, NHEADS);
        attn_f16<<<grid, 256, ATTN_SMEM_BYTES>>>(xqkv, xo);
    }
    // 3) out = xo @ Wo  (fp32 out)
    {
        dim3 grid(DIM / 128, SEQ / 128);
        gemm_f16<<<grid, 256, GEMM_SMEM_BYTES>>>(xo, woT, out, DIM, DIM, 0);
    }
}

// round 8
// speedup vs baseline: 1.8448x; 1.0865x over previous
#include <cuda_runtime.h>
#include <cuda_fp16.h>
#include <cstdint>
#include <math.h>

// ---------------------------------------------------------------------------
// Problem constants
// ---------------------------------------------------------------------------
#define SEQ     4096
#define DIM     2048
#define NHEADS  16
#define HDIM    128
#define QKV_N   6144

// ---------------------------------------------------------------------------
// Scratch (device globals; allocation forbidden)
// ---------------------------------------------------------------------------
__device__ __align__(16) __half g_xh   [(size_t)SEQ * DIM];
__device__ __align__(16) __half g_wqkvT[(size_t)QKV_N * DIM];   // Wqkv^T (Q-third pre-scaled by 1/sqrt(d))
__device__ __align__(16) __half g_woT  [(size_t)DIM * DIM];
__device__ __align__(16) __half g_xqkv [(size_t)SEQ * QKV_N];
__device__ __align__(16) __half g_xo   [(size_t)SEQ * DIM];

// ---------------------------------------------------------------------------
// Helpers
// ---------------------------------------------------------------------------
__device__ __forceinline__ void mma_f16(float* c, const uint32_t* a, const uint32_t* b) {
    asm volatile(
        "mma.sync.aligned.m16n8k16.row.col.f32.f16.f16.f32 "
        "{%0,%1,%2,%3}, {%4,%5,%6,%7}, {%8,%9}, {%0,%1,%2,%3};"
        : "+f"(c[0]), "+f"(c[1]), "+f"(c[2]), "+f"(c[3])
        : "r"(a[0]), "r"(a[1]), "r"(a[2]), "r"(a[3]), "r"(b[0]), "r"(b[1]));
}

__device__ __forceinline__ void ldsm_x4(uint32_t* r, uint32_t addr) {
    asm volatile("ldmatrix.sync.aligned.m8n8.x4.shared.b16 {%0,%1,%2,%3}, [%4];"
                 : "=r"(r[0]), "=r"(r[1]), "=r"(r[2]), "=r"(r[3]) : "r"(addr));
}
__device__ __forceinline__ void ldsm_x4_t(uint32_t* r, uint32_t addr) {
    asm volatile("ldmatrix.sync.aligned.m8n8.x4.trans.shared.b16 {%0,%1,%2,%3}, [%4];"
                 : "=r"(r[0]), "=r"(r[1]), "=r"(r[2]), "=r"(r[3]) : "r"(addr));
}

__device__ __forceinline__ void cp_async16(uint32_t dst, const void* src) {
    asm volatile("cp.async.cg.shared.global [%0], [%1], 16;" :: "r"(dst), "l"(src));
}
__device__ __forceinline__ void cp_commit() { asm volatile("cp.async.commit_group;"); }
template<int N> __device__ __forceinline__ void cp_wait() {
    asm volatile("cp.async.wait_group %0;" :: "n"(N));
}

// FMA-only exp, valid for x <= 0. Keeps the MUFU pipe idle.
__device__ __forceinline__ float fast_exp(float x) {
    float t = fmaxf(x * 1.4426950408889634f, -126.0f);
    float z = t + 12582912.0f;
    int   zi = __float_as_int(z);
    float n = z - 12582912.0f;
    float f = t - n;
    float p = fmaf(f, 1.3333558e-3f, 9.6181291e-3f);
    p = fmaf(f, p, 5.5504109e-2f);
    p = fmaf(f, p, 2.4022651e-1f);
    p = fmaf(f, p, 6.9314718e-1f);
    p = fmaf(f, p, 1.0f);
    return __int_as_float((zi << 23) + 0x3F800000) * p;
}

// ---------------------------------------------------------------------------
// Prep kernels
// ---------------------------------------------------------------------------
__global__ void f2h_kernel(const float* __restrict__ in, __half* __restrict__ out, int n4)
{
    int i = blockIdx.x * blockDim.x + threadIdx.x;
    if (i < n4) {
        float4 v = ((const float4*)in)[i];
        __half2* o = (__half2*)out + 2 * (size_t)i;
        o[0] = __floats2half2_rn(v.x, v.y);
        o[1] = __floats2half2_rn(v.z, v.w);
    }
}

__global__ void transpose_h_kernel(const float* __restrict__ W, __half* __restrict__ Wt,
                                   int K, int N, int scaleLimit, float scale)
{
    __shared__ float tile[32][33];
    const int n0 = blockIdx.x * 32;
    const int k0 = blockIdx.y * 32;
    const int tx = threadIdx.x, ty = threadIdx.y;
#pragma unroll
    for (int dy = ty; dy < 32; dy += 8)
        tile[dy][tx] = W[(size_t)(k0 + dy) * N + n0 + tx];
    __syncthreads();
#pragma unroll
    for (int dy = ty; dy < 32; dy += 8) {
        int n = n0 + dy;
        float s = (n < scaleLimit) ? scale : 1.0f;
        Wt[(size_t)n * K + k0 + tx] = __float2half_rn(tile[tx][dy] * s);
    }
}

// ---------------------------------------------------------------------------
// FP16 GEMM (unchanged from R7): C[M,N] = A[M,K] @ Bt[N,K]^T, fp32 accumulate.
// ---------------------------------------------------------------------------
#define GKH 64
#define GSTG_B 36864
#define GEMM_SMEM_BYTES (3 * GSTG_B)

__global__ __launch_bounds__(256, 2)
void gemm_f16(const __half* __restrict__ A, const __half* __restrict__ Bt,
              void* __restrict__ Cv, int N, int K, int out_half)
{
    extern __shared__ char smc[];
    const uint32_t sb = (uint32_t)__cvta_generic_to_shared(smc);

    const int tid  = threadIdx.x;
    const int lane = tid & 31;
    const int wid  = tid >> 5;
    const int g    = lane >> 2;
    const int tig  = lane & 3;
    const int rowW = (wid & 1) * 64;
    const int colW = (wid >> 1) * 32;
    const int bm = blockIdx.y * 128;
    const int bn = blockIdx.x * 128;

    const __half* grow = (tid < 128) ? (A + (size_t)(bm + tid) * K)
                                     : (Bt + (size_t)(bn + tid - 128) * K);
    const uint32_t drow = sb + (uint32_t)tid * 144u;

    const int arow_l = (lane & 7) + ((lane >> 3) & 1) * 8;
    const uint32_t lpA = (uint32_t)arow_l * 144u + (uint32_t)(lane >> 4) * 16u;
    const int brow_l = (lane >> 4) * 8 + (lane & 7);
    const uint32_t lpB = (uint32_t)brow_l * 144u + (uint32_t)((lane >> 3) & 1) * 16u;

    const uint32_t aBase0 = sb + (uint32_t)rowW * 144u + lpA;
    const uint32_t bBase0 = sb + (uint32_t)(128 + colW) * 144u + lpB;

    float acc[16][4];
#pragma unroll
    for (int i = 0; i < 16; i++) { acc[i][0] = acc[i][1] = acc[i][2] = acc[i][3] = 0.f; }

    const int nIter = K / GKH;

#define GEMM_ISSUE(IT, BUF) do {                                               \
        const __half* _gp = grow + (IT) * GKH;                                 \
        uint32_t _d = drow + (uint32_t)((BUF) * GSTG_B);                       \
        _Pragma("unroll")                                                      \
        for (int _j = 0; _j < 8; _j++) cp_async16(_d + _j * 16u, _gp + _j * 8);\
        cp_commit();                                                           \
    } while (0)

    GEMM_ISSUE(0, 0);
    GEMM_ISSUE(1, 1);

    int buf = 0;
    for (int it = 0; it < nIter; ++it) {
        if (it < nIter - 1) cp_wait<1>(); else cp_wait<0>();
        __syncthreads();

        if (it + 2 < nIter) {
            const int ibuf = (buf + 2 >= 3) ? buf - 1 : buf + 2;
            GEMM_ISSUE(it + 2, ibuf);
        }

        const uint32_t aB = aBase0 + (uint32_t)(buf * GSTG_B);
        const uint32_t bB = bBase0 + (uint32_t)(buf * GSTG_B);

#pragma unroll
        for (int ks = 0; ks < 4; ks++) {
            uint32_t af[4][4], bf[4][2];
#pragma unroll
            for (int mt = 0; mt < 4; mt++)
                ldsm_x4(af[mt], aB + (uint32_t)(mt * 16 * 144 + ks * 32));
#pragma unroll
            for (int ng = 0; ng < 2; ng++) {
                uint32_t t4[4];
                ldsm_x4(t4, bB + (uint32_t)(ng * 16 * 144 + ks * 32));
                bf[2 * ng][0]     = t4[0];
                bf[2 * ng][1]     = t4[1];
                bf[2 * ng + 1][0] = t4[2];
                bf[2 * ng + 1][1] = t4[3];
            }
#pragma unroll
            for (int mt = 0; mt < 4; mt++)
#pragma unroll
                for (int nt = 0; nt < 4; nt++)
                    mma_f16(acc[mt * 4 + nt], af[mt], bf[nt]);
        }
        buf = (buf + 1 == 3) ? 0 : buf + 1;
    }

    if (out_half) {
        __half* C = (__half*)Cv;
#pragma unroll
        for (int mt = 0; mt < 4; mt++) {
            const int r0 = bm + rowW + mt * 16 + g;
#pragma unroll
            for (int nt = 0; nt < 4; nt++) {
                const int col = bn + colW + nt * 8 + 2 * tig;
                *(__half2*)(C + (size_t)r0 * N + col) =
                    __floats2half2_rn(acc[mt * 4 + nt][0], acc[mt * 4 + nt][1]);
                *(__half2*)(C + (size_t)(r0 + 8) * N + col) =
                    __floats2half2_rn(acc[mt * 4 + nt][2], acc[mt * 4 + nt][3]);
            }
        }
    } else {
        float* C = (float*)Cv;
#pragma unroll
        for (int mt = 0; mt < 4; mt++) {
            const int r0 = bm + rowW + mt * 16 + g;
#pragma unroll
            for (int nt = 0; nt < 4; nt++) {
                const int col = bn + colW + nt * 8 + 2 * tig;
                *(float2*)(C + (size_t)r0 * N + col) =
                    make_float2(acc[mt * 4 + nt][0], acc[mt * 4 + nt][1]);
                *(float2*)(C + (size_t)(r0 + 8) * N + col) =
                    make_float2(acc[mt * 4 + nt][2], acc[mt * 4 + nt][3]);
            }
        }
    }
#undef GEMM_ISSUE
}

// ---------------------------------------------------------------------------
// FP16 flash attention, PV(t) overlapped with S(t+1) in one mma phase.
// Br=Bc=64, d=128, 256 threads (8 warps), 2 CTAs/SM, 2 barriers/iter.
// K and V both double-buffered. 1/sqrt(d) folded into Wq at prep.
// ---------------------------------------------------------------------------
#define BR 64
#define BC 64
#define NT (SEQ / BC)
// byte offsets (Q/K/V rows = 136 halves = 272B; P rows = 72 halves = 144B)
#define AQ   0
#define AK0  17408
#define AK1  34816
#define AV0  52224
#define AV1  69632
#define AP   87040
#define APM  96256
#define APS  97280
#define AMS  98304
#define ALS  98816
#define ATTN_SMEM_BYTES 99328

__global__ __launch_bounds__(256, 2)
void attn_f16(const __half* __restrict__ xqkv, __half* __restrict__ xo)
{
    extern __shared__ char smc[];
    const uint32_t sb = (uint32_t)__cvta_generic_to_shared(smc);
    float* pmax = (float*)(smc + APM);
    float* psum = (float*)(smc + APS);
    float* m_s  = (float*)(smc + AMS);
    float* l_s  = (float*)(smc + ALS);

    const int tid  = threadIdx.x;
    const int lane = tid & 31;
    const int wid  = tid >> 5;
    const int g    = lane >> 2;
    const int tig  = lane & 3;
    const int wM   = wid & 1;            // 0..1 -> 32-row band
    const int wN   = wid >> 1;           // 0..3 -> 16-col (S) / 32-col (PV) band

    const int h  = blockIdx.y;
    const int q0 = blockIdx.x * BR;

    const __half* Qg = xqkv + (size_t)q0 * QKV_N + h * HDIM;
    const __half* Kg = xqkv + 2048 + h * HDIM;
    const __half* Vg = xqkv + 4096 + h * HDIM;

    const int crow = tid >> 2;
    const int cbo  = (tid & 3) * 64;

    const int arow_l = (lane & 7) + ((lane >> 3) & 1) * 8;
    const uint32_t lpA272 = (uint32_t)arow_l * 272u + (uint32_t)(lane >> 4) * 16u;
    const uint32_t lpA144 = (uint32_t)arow_l * 144u + (uint32_t)(lane >> 4) * 16u;
    const int brow_l = (lane >> 4) * 8 + (lane & 7);
    const uint32_t lpB272 = (uint32_t)brow_l * 272u + (uint32_t)((lane >> 3) & 1) * 16u;

    const uint32_t q_lm   = sb + AQ + (uint32_t)(32 * wM) * 272u + lpA272;
    const uint32_t k_lmBo = (uint32_t)(16 * wN) * 272u + lpB272;
    const uint32_t p_lm   = sb + AP + (uint32_t)(32 * wM) * 144u + lpA144;

    float sacc[4][4];
    float oacc[8][4];
#pragma unroll
    for (int i = 0; i < 8; i++) { oacc[i][0] = oacc[i][1] = oacc[i][2] = oacc[i][3] = 0.f; }

    // ---- S(t) = Q @ K(t)^T, warp tile 32x16, into sacc ----
    auto compute_S = [&](uint32_t k_lm) {
#pragma unroll
        for (int i = 0; i < 4; i++) { sacc[i][0] = sacc[i][1] = sacc[i][2] = sacc[i][3] = 0.f; }
#pragma unroll
        for (int ks = 0; ks < 8; ks++) {
            uint32_t af[2][4], bf[2][2];
#pragma unroll
            for (int mt = 0; mt < 2; mt++)
                ldsm_x4(af[mt], q_lm + (uint32_t)(mt * 16 * 272 + ks * 32));
            {
                uint32_t t4[4];
                ldsm_x4(t4, k_lm + (uint32_t)(ks * 32));
                bf[0][0] = t4[0]; bf[0][1] = t4[1];
                bf[1][0] = t4[2]; bf[1][1] = t4[3];
            }
#pragma unroll
            for (int mt = 0; mt < 2; mt++)
#pragma unroll
                for (int nt = 0; nt < 2; nt++)
                    mma_f16(sacc[mt * 2 + nt], af[mt], bf[nt]);
        }
    };

    // ---- prologue: group0 = Q + K(0); group1 = V(0) + K(1) ----
    {
        const __half* qs = Qg + (size_t)crow * QKV_N + cbo / 2;
        const __half* ks = Kg + (size_t)crow * QKV_N + cbo / 2;
        const uint32_t qd = sb + AQ  + (uint32_t)crow * 272u + cbo;
        const uint32_t kd = sb + AK0 + (uint32_t)crow * 272u + cbo;
#pragma unroll
        for (int j = 0; j < 4; j++) cp_async16(qd + j * 16u, qs + j * 8);
#pragma unroll
        for (int j = 0; j < 4; j++) cp_async16(kd + j * 16u, ks + j * 8);
        cp_commit();

        const __half* vs = Vg + (size_t)crow * QKV_N + cbo / 2;
        const __half* k1 = Kg + (size_t)(BC + crow) * QKV_N + cbo / 2;
        const uint32_t vd = sb + AV0 + (uint32_t)crow * 272u + cbo;
        const uint32_t k1d = sb + AK1 + (uint32_t)crow * 272u + cbo;
#pragma unroll
        for (int j = 0; j < 4; j++) cp_async16(vd + j * 16u, vs + j * 8);
#pragma unroll
        for (int j = 0; j < 4; j++) cp_async16(k1d + j * 16u, k1 + j * 8);
        cp_commit();
    }
    if (tid < BR) { m_s[tid] = -INFINITY; l_s[tid] = 0.f; }   // slot 0

    cp_wait<1>();            // group0 (Q, K0) resident
    __syncthreads();

    compute_S(sb + AK0 + k_lmBo);        // S(0)

    for (int t = 0; t < NT; ++t) {
        const int cur = t & 1, nxt = cur ^ 1;

        // ---- softmax(t), part 1: per-row tile max -> pmax ----
#pragma unroll
        for (int mt = 0; mt < 2; mt++)
#pragma unroll
            for (int hh = 0; hh < 2; hh++) {
                float a0 = sacc[2 * mt][2 * hh],     a1 = sacc[2 * mt][2 * hh + 1];
                float a2 = sacc[2 * mt + 1][2 * hh], a3 = sacc[2 * mt + 1][2 * hh + 1];
                float mx = fmaxf(fmaxf(a0, a1), fmaxf(a2, a3));
                mx = fmaxf(mx, __shfl_xor_sync(0xffffffffu, mx, 1));
                mx = fmaxf(mx, __shfl_xor_sync(0xffffffffu, mx, 2));
                if (tig == 0) pmax[wN * 64 + 32 * wM + 16 * mt + g + 8 * hh] = mx;
            }
        __syncthreads();     // B1: pmax ready (also: all warps done with mma(t-1))

        // ---- softmax(t), part 2: exp, P store, psum, corr ----
        float corr[2][2];
#pragma unroll
        for (int mt = 0; mt < 2; mt++)
#pragma unroll
            for (int hh = 0; hh < 2; hh++) {
                const int r = 32 * wM + 16 * mt + g + 8 * hh;
                const float mold = m_s[cur * 64 + r];
                float mn = fmaxf(fmaxf(pmax[r], pmax[64 + r]),
                                 fmaxf(pmax[128 + r], pmax[192 + r]));
                mn = fmaxf(mold, mn);
                const float co = fast_exp(mold - mn);
                corr[mt][hh] = co;
                if (wN == 0 && tig == 0) m_s[nxt * 64 + r] = mn;

                float e0 = fast_exp(sacc[2 * mt][2 * hh] - mn);
                float e1 = fast_exp(sacc[2 * mt][2 * hh + 1] - mn);
                float e2 = fast_exp(sacc[2 * mt + 1][2 * hh] - mn);
                float e3 = fast_exp(sacc[2 * mt + 1][2 * hh + 1] - mn);
                float sum = (e0 + e1) + (e2 + e3);
                sum += __shfl_xor_sync(0xffffffffu, sum, 1);
                sum += __shfl_xor_sync(0xffffffffu, sum, 2);
                if (tig == 0) psum[wN * 64 + r] = sum;

                char* pr = smc + AP + (size_t)r * 144;
                *(__half2*)(pr + (16 * wN + 2 * tig) * 2)     = __floats2half2_rn(e0, e1);
                *(__half2*)(pr + (16 * wN + 8 + 2 * tig) * 2) = __floats2half2_rn(e2, e3);
            }

        cp_wait<0>();        // V(t) and K(t+1) resident
        __syncthreads();     // B2: P(t), psum visible; loads visible

        if (wN == 0 && tig == 0) {
#pragma unroll
            for (int mt = 0; mt < 2; mt++)
#pragma unroll
                for (int hh = 0; hh < 2; hh++) {
                    const int r = 32 * wM + 16 * mt + g + 8 * hh;
                    l_s[nxt * 64 + r] = l_s[cur * 64 + r] * corr[mt][hh] +
                        ((psum[r] + psum[64 + r]) + (psum[128 + r] + psum[192 + r]));
                }
        }

        // ---- issue V(t+1) -> buf nxt, K(t+2) -> buf cur ----
        if (t + 1 < NT) {
            const __half* vs = Vg + (size_t)((t + 1) * BC + crow) * QKV_N + cbo / 2;
            const uint32_t vd = sb + (nxt ? AV1 : AV0) + (uint32_t)crow * 272u + cbo;
#pragma unroll
            for (int j = 0; j < 4; j++) cp_async16(vd + j * 16u, vs + j * 8);
            if (t + 2 < NT) {
                const __half* ks = Kg + (size_t)((t + 2) * BC + crow) * QKV_N + cbo / 2;
                const uint32_t kd = sb + (cur ? AK1 : AK0) + (uint32_t)crow * 272u + cbo;
#pragma unroll
                for (int j = 0; j < 4; j++) cp_async16(kd + j * 16u, ks + j * 8);
            }
            cp_commit();
        }

        // ---- mma phase: PV(t) + S(t+1), independent accumulator sets ----
#pragma unroll
        for (int mt = 0; mt < 2; mt++)
#pragma unroll
            for (int nt = 0; nt < 4; nt++) {
                float* a = oacc[mt * 4 + nt];
                a[0] *= corr[mt][0]; a[1] *= corr[mt][0];
                a[2] *= corr[mt][1]; a[3] *= corr[mt][1];
            }

        const uint32_t v_lm = sb + (cur ? AV1 : AV0) + lpA272;
#pragma unroll
        for (int ks = 0; ks < 4; ks++) {             // PV: 4 x k16 over Bc=64
            uint32_t paf[2][4], vbf[4][2];
#pragma unroll
            for (int mt = 0; mt < 2; mt++)
                ldsm_x4(paf[mt], p_lm + (uint32_t)(mt * 16 * 144 + ks * 32));
#pragma unroll
            for (int ng = 0; ng < 2; ng++) {
                uint32_t t4[4];
                ldsm_x4_t(t4, v_lm + (uint32_t)(ks * 16 * 272 + (32 * wN + ng * 16) * 2));
                vbf[2 * ng][0]     = t4[0];
                vbf[2 * ng][1]     = t4[1];
                vbf[2 * ng + 1][0] = t4[2];
                vbf[2 * ng + 1][1] = t4[3];
            }
#pragma unroll
            for (int mt = 0; mt < 2; mt++)
#pragma unroll
                for (int nt = 0; nt < 4; nt++)
                    mma_f16(oacc[mt * 4 + nt], paf[mt], vbf[nt]);
        }

        if (t + 1 < NT)
            compute_S(sb + (nxt ? AK1 : AK0) + k_lmBo);   // S(t+1)
    }

    // ---- epilogue: normalize, write fp16 xo ----
    __syncthreads();
    const int fin = NT & 1;              // = 0 for NT=64
#pragma unroll
    for (int mt = 0; mt < 2; mt++) {
        const int r0 = 32 * wM + 16 * mt + g;
        const float il0 = 1.f / l_s[fin * 64 + r0];
        const float il1 = 1.f / l_s[fin * 64 + r0 + 8];
#pragma unroll
        for (int nt = 0; nt < 4; nt++) {
            const int col = h * HDIM + 32 * wN + 8 * nt + 2 * tig;
            *(__half2*)(xo + (size_t)(q0 + r0) * DIM + col) =
                __floats2half2_rn(oacc[mt * 4 + nt][0] * il0, oacc[mt * 4 + nt][1] * il0);
            *(__half2*)(xo + (size_t)(q0 + r0 + 8) * DIM + col) =
                __floats2half2_rn(oacc[mt * 4 + nt][2] * il1, oacc[mt * 4 + nt][3] * il1);
        }
    }
}

// ---------------------------------------------------------------------------
// Launch
// ---------------------------------------------------------------------------
extern "C" void kernel_launch(void* const* d_in, const int* in_sizes, int n_in,
                              void* d_out, int out_size)
{
    const float* x    = (const float*)d_in[0];   // [4096, 2048]
    const float* Wqkv = (const float*)d_in[1];   // [2048, 6144]
    const float* Wo   = (const float*)d_in[2];   // [2048, 2048]
    float* out = (float*)d_out;                  // [4096, 2048]

    __half *xh, *wqkvT, *woT, *xqkv, *xo;
    cudaGetSymbolAddress((void**)&xh,    g_xh);
    cudaGetSymbolAddress((void**)&wqkvT, g_wqkvT);
    cudaGetSymbolAddress((void**)&woT,   g_woT);
    cudaGetSymbolAddress((void**)&xqkv,  g_xqkv);
    cudaGetSymbolAddress((void**)&xo,    g_xo);

    cudaFuncSetAttribute(gemm_f16, cudaFuncAttributeMaxDynamicSharedMemorySize,
                         GEMM_SMEM_BYTES);
    cudaFuncSetAttribute(attn_f16, cudaFuncAttributeMaxDynamicSharedMemorySize,
                         ATTN_SMEM_BYTES);

    // 0) prep
    f2h_kernel<<<(SEQ * DIM / 4) / 256, 256>>>(x, xh, SEQ * DIM / 4);
    {
        dim3 blk(32, 8);
        transpose_h_kernel<<<dim3(QKV_N / 32, DIM / 32), blk>>>(
            Wqkv, wqkvT, DIM, QKV_N, NHEADS * HDIM, 0.08838834764831845f);
        transpose_h_kernel<<<dim3(DIM / 32, DIM / 32), blk>>>(
            Wo, woT, DIM, DIM, 0, 1.0f);
    }
    // 1) xqkv = x @ Wqkv (fp16 out)
    {
        dim3 grid(QKV_N / 128, SEQ / 128);
        gemm_f16<<<grid, 256, GEMM_SMEM_BYTES>>>(xh, wqkvT, xqkv, QKV_N, DIM, 1);
    }
    // 2) flash attention -> xo (fp16)
    {
        dim3 grid(SEQ / BR, NHEADS);
        attn_f16<<<grid, 256, ATTN_SMEM_BYTES>>>(xqkv, xo);
    }
    // 3) out = xo @ Wo (fp32 out)
    {
        dim3 grid(DIM / 128, SEQ / 128);
        gemm_f16<<<grid, 256, GEMM_SMEM_BYTES>>>(xo, woT, out, DIM, DIM, 0);
    }
}

// round 9
// speedup vs baseline: 2.2514x; 1.2204x over previous
#include <cuda_runtime.h>
#include <cuda_fp16.h>
#include <cstdint>
#include <math.h>

// ---------------------------------------------------------------------------
// Problem constants
// ---------------------------------------------------------------------------
#define SEQ     4096
#define DIM     2048
#define NHEADS  16
#define HDIM    128
#define QKV_N   6144

// ---------------------------------------------------------------------------
// Scratch (device globals; allocation forbidden)
// ---------------------------------------------------------------------------
__device__ __align__(16) __half g_xh   [(size_t)SEQ * DIM];
__device__ __align__(16) __half g_wqkvT[(size_t)QKV_N * DIM];   // Wqkv^T (Q-third pre-scaled by 1/sqrt(d))
__device__ __align__(16) __half g_woT  [(size_t)DIM * DIM];
__device__ __align__(16) __half g_xqkv [(size_t)SEQ * QKV_N];
__device__ __align__(16) __half g_xo   [(size_t)SEQ * DIM];

// ---------------------------------------------------------------------------
// Helpers
// ---------------------------------------------------------------------------
__device__ __forceinline__ void mma_f16(float* c, const uint32_t* a, const uint32_t* b) {
    asm volatile(
        "mma.sync.aligned.m16n8k16.row.col.f32.f16.f16.f32 "
        "{%0,%1,%2,%3}, {%4,%5,%6,%7}, {%8,%9}, {%0,%1,%2,%3};"
        : "+f"(c[0]), "+f"(c[1]), "+f"(c[2]), "+f"(c[3])
        : "r"(a[0]), "r"(a[1]), "r"(a[2]), "r"(a[3]), "r"(b[0]), "r"(b[1]));
}

__device__ __forceinline__ void ldsm_x4(uint32_t* r, uint32_t addr) {
    asm volatile("ldmatrix.sync.aligned.m8n8.x4.shared.b16 {%0,%1,%2,%3}, [%4];"
                 : "=r"(r[0]), "=r"(r[1]), "=r"(r[2]), "=r"(r[3]) : "r"(addr));
}
__device__ __forceinline__ void ldsm_x4_t(uint32_t* r, uint32_t addr) {
    asm volatile("ldmatrix.sync.aligned.m8n8.x4.trans.shared.b16 {%0,%1,%2,%3}, [%4];"
                 : "=r"(r[0]), "=r"(r[1]), "=r"(r[2]), "=r"(r[3]) : "r"(addr));
}

__device__ __forceinline__ void cp_async16(uint32_t dst, const void* src) {
    asm volatile("cp.async.cg.shared.global [%0], [%1], 16;" :: "r"(dst), "l"(src));
}
__device__ __forceinline__ void cp_commit() { asm volatile("cp.async.commit_group;"); }
template<int N> __device__ __forceinline__ void cp_wait() {
    asm volatile("cp.async.wait_group %0;" :: "n"(N));
}

// FMA-only exp, valid for x <= 0. Keeps the MUFU pipe idle.
__device__ __forceinline__ float fast_exp(float x) {
    float t = fmaxf(x * 1.4426950408889634f, -126.0f);
    float z = t + 12582912.0f;
    int   zi = __float_as_int(z);
    float n = z - 12582912.0f;
    float f = t - n;
    float p = fmaf(f, 1.3333558e-3f, 9.6181291e-3f);
    p = fmaf(f, p, 5.5504109e-2f);
    p = fmaf(f, p, 2.4022651e-1f);
    p = fmaf(f, p, 6.9314718e-1f);
    p = fmaf(f, p, 1.0f);
    return __int_as_float((zi << 23) + 0x3F800000) * p;
}

// ---------------------------------------------------------------------------
// Prep kernels
// ---------------------------------------------------------------------------
__global__ void f2h_kernel(const float* __restrict__ in, __half* __restrict__ out, int n4)
{
    int i = blockIdx.x * blockDim.x + threadIdx.x;
    if (i < n4) {
        float4 v = ((const float4*)in)[i];
        __half2* o = (__half2*)out + 2 * (size_t)i;
        o[0] = __floats2half2_rn(v.x, v.y);
        o[1] = __floats2half2_rn(v.z, v.w);
    }
}

__global__ void transpose_h_kernel(const float* __restrict__ W, __half* __restrict__ Wt,
                                   int K, int N, int scaleLimit, float scale)
{
    __shared__ float tile[32][33];
    const int n0 = blockIdx.x * 32;
    const int k0 = blockIdx.y * 32;
    const int tx = threadIdx.x, ty = threadIdx.y;
#pragma unroll
    for (int dy = ty; dy < 32; dy += 8)
        tile[dy][tx] = W[(size_t)(k0 + dy) * N + n0 + tx];
    __syncthreads();
#pragma unroll
    for (int dy = ty; dy < 32; dy += 8) {
        int n = n0 + dy;
        float s = (n < scaleLimit) ? scale : 1.0f;
        Wt[(size_t)n * K + k0 + tx] = __float2half_rn(tile[tx][dy] * s);
    }
}

// ---------------------------------------------------------------------------
// FP16 GEMM, high-occupancy variant: C[M,N] = A[M,K] @ Bt[N,K]^T.
// CTA tile 128x64, warp tile 32x32 (8 warps, 4Mx2N), K-chunk 64 halves,
// 2-stage cp.async, ONE barrier/iter, __launch_bounds__(256,3) -> 24 warps/SM.
// smem rows 144B (72 halves; %32B==16 -> conflict-free ldmatrix phases).
// ---------------------------------------------------------------------------
#define GKH 64
#define GROWS 192                       // 128 A rows + 64 B rows
#define GSTG_B (GROWS * 144)            // 27648 B per stage
#define GEMM_SMEM_BYTES (2 * GSTG_B)    // 55296 B -> 3 CTAs/SM

__global__ __launch_bounds__(256, 3)
void gemm_f16(const __half* __restrict__ A, const __half* __restrict__ Bt,
              void* __restrict__ Cv, int N, int K, int out_half)
{
    extern __shared__ char smc[];
    const uint32_t sb = (uint32_t)__cvta_generic_to_shared(smc);

    const int tid  = threadIdx.x;
    const int lane = tid & 31;
    const int wid  = tid >> 5;
    const int g    = lane >> 2;
    const int tig  = lane & 3;
    const int wM   = wid & 3;            // 0..3 -> 32-row band
    const int wN   = wid >> 2;           // 0..1 -> 32-col band
    const int bm = blockIdx.y * 128;
    const int bn = blockIdx.x * 64;

    // cp.async: thread covers rows (tid>>3)+32j, chunk (tid&7)*16B, j=0..5
    const int r0c = tid >> 3;            // 0..31
    const int co  = (tid & 7) * 8;       // halves offset within row
    const __half* gp[6];
#pragma unroll
    for (int j = 0; j < 6; j++) {
        int row = r0c + 32 * j;
        gp[j] = (row < 128) ? (A + (size_t)(bm + row) * K + co)
                            : (Bt + (size_t)(bn + row - 128) * K + co);
    }
    const uint32_t cdst = sb + (uint32_t)r0c * 144u + (uint32_t)(tid & 7) * 16u;

    // ldmatrix lane parts
    const int arow_l = (lane & 7) + ((lane >> 3) & 1) * 8;
    const uint32_t a_lm0 = sb + (uint32_t)(32 * wM + arow_l) * 144u
                              + (uint32_t)(lane >> 4) * 16u;
    const int brow_l = (lane >> 4) * 8 + (lane & 7);
    const uint32_t b_lm0 = sb + (uint32_t)(128 + 32 * wN + brow_l) * 144u
                              + (uint32_t)((lane >> 3) & 1) * 16u;

    float acc[8][4];
#pragma unroll
    for (int i = 0; i < 8; i++) { acc[i][0] = acc[i][1] = acc[i][2] = acc[i][3] = 0.f; }

    const int nIter = K / GKH;           // 32

#define GEMM_ISSUE(IT, BUF) do {                                               \
        uint32_t _d = cdst + (uint32_t)((BUF) * GSTG_B);                       \
        _Pragma("unroll")                                                      \
        for (int _j = 0; _j < 6; _j++)                                         \
            cp_async16(_d + _j * (32u * 144u), gp[_j] + (IT) * GKH);           \
        cp_commit();                                                           \
    } while (0)

    GEMM_ISSUE(0, 0);

    for (int it = 0; it < nIter; ++it) {
        cp_wait<0>();
        __syncthreads();                 // data visible + buf (it+1)&1 free

        if (it + 1 < nIter) GEMM_ISSUE(it + 1, (it + 1) & 1);

        const uint32_t a_lm = a_lm0 + (uint32_t)((it & 1) * GSTG_B);
        const uint32_t b_lm = b_lm0 + (uint32_t)((it & 1) * GSTG_B);

#pragma unroll
        for (int ks = 0; ks < 4; ks++) {            // 4 x k16
            uint32_t af[2][4], bf[4][2];
#pragma unroll
            for (int mt = 0; mt < 2; mt++)
                ldsm_x4(af[mt], a_lm + (uint32_t)(mt * 16 * 144 + ks * 32));
#pragma unroll
            for (int ng = 0; ng < 2; ng++) {
                uint32_t t4[4];
                ldsm_x4(t4, b_lm + (uint32_t)(ng * 16 * 144 + ks * 32));
                bf[2 * ng][0]     = t4[0];
                bf[2 * ng][1]     = t4[1];
                bf[2 * ng + 1][0] = t4[2];
                bf[2 * ng + 1][1] = t4[3];
            }
#pragma unroll
            for (int mt = 0; mt < 2; mt++)
#pragma unroll
                for (int nt = 0; nt < 4; nt++)
                    mma_f16(acc[mt * 4 + nt], af[mt], bf[nt]);
        }
    }

    if (out_half) {
        __half* C = (__half*)Cv;
#pragma unroll
        for (int mt = 0; mt < 2; mt++) {
            const int r0 = bm + 32 * wM + mt * 16 + g;
#pragma unroll
            for (int nt = 0; nt < 4; nt++) {
                const int col = bn + 32 * wN + nt * 8 + 2 * tig;
                *(__half2*)(C + (size_t)r0 * N + col) =
                    __floats2half2_rn(acc[mt * 4 + nt][0], acc[mt * 4 + nt][1]);
                *(__half2*)(C + (size_t)(r0 + 8) * N + col) =
                    __floats2half2_rn(acc[mt * 4 + nt][2], acc[mt * 4 + nt][3]);
            }
        }
    } else {
        float* C = (float*)Cv;
#pragma unroll
        for (int mt = 0; mt < 2; mt++) {
            const int r0 = bm + 32 * wM + mt * 16 + g;
#pragma unroll
            for (int nt = 0; nt < 4; nt++) {
                const int col = bn + 32 * wN + nt * 8 + 2 * tig;
                *(float2*)(C + (size_t)r0 * N + col) =
                    make_float2(acc[mt * 4 + nt][0], acc[mt * 4 + nt][1]);
                *(float2*)(C + (size_t)(r0 + 8) * N + col) =
                    make_float2(acc[mt * 4 + nt][2], acc[mt * 4 + nt][3]);
            }
        }
    }
#undef GEMM_ISSUE
}

// ---------------------------------------------------------------------------
// FP16 flash attention (unchanged from R8): PV(t) overlapped with S(t+1),
// Br=Bc=64, 256 threads, 2 CTAs/SM, 2 barriers/iter, K/V double-buffered.
// ---------------------------------------------------------------------------
#define BR 64
#define BC 64
#define NT (SEQ / BC)
#define AQ   0
#define AK0  17408
#define AK1  34816
#define AV0  52224
#define AV1  69632
#define AP   87040
#define APM  96256
#define APS  97280
#define AMS  98304
#define ALS  98816
#define ATTN_SMEM_BYTES 99328

__global__ __launch_bounds__(256, 2)
void attn_f16(const __half* __restrict__ xqkv, __half* __restrict__ xo)
{
    extern __shared__ char smc[];
    const uint32_t sb = (uint32_t)__cvta_generic_to_shared(smc);
    float* pmax = (float*)(smc + APM);
    float* psum = (float*)(smc + APS);
    float* m_s  = (float*)(smc + AMS);
    float* l_s  = (float*)(smc + ALS);

    const int tid  = threadIdx.x;
    const int lane = tid & 31;
    const int wid  = tid >> 5;
    const int g    = lane >> 2;
    const int tig  = lane & 3;
    const int wM   = wid & 1;
    const int wN   = wid >> 1;

    const int h  = blockIdx.y;
    const int q0 = blockIdx.x * BR;

    const __half* Qg = xqkv + (size_t)q0 * QKV_N + h * HDIM;
    const __half* Kg = xqkv + 2048 + h * HDIM;
    const __half* Vg = xqkv + 4096 + h * HDIM;

    const int crow = tid >> 2;
    const int cbo  = (tid & 3) * 64;

    const int arow_l = (lane & 7) + ((lane >> 3) & 1) * 8;
    const uint32_t lpA272 = (uint32_t)arow_l * 272u + (uint32_t)(lane >> 4) * 16u;
    const uint32_t lpA144 = (uint32_t)arow_l * 144u + (uint32_t)(lane >> 4) * 16u;
    const int brow_l = (lane >> 4) * 8 + (lane & 7);
    const uint32_t lpB272 = (uint32_t)brow_l * 272u + (uint32_t)((lane >> 3) & 1) * 16u;

    const uint32_t q_lm   = sb + AQ + (uint32_t)(32 * wM) * 272u + lpA272;
    const uint32_t k_lmBo = (uint32_t)(16 * wN) * 272u + lpB272;
    const uint32_t p_lm   = sb + AP + (uint32_t)(32 * wM) * 144u + lpA144;

    float sacc[4][4];
    float oacc[8][4];
#pragma unroll
    for (int i = 0; i < 8; i++) { oacc[i][0] = oacc[i][1] = oacc[i][2] = oacc[i][3] = 0.f; }

    auto compute_S = [&](uint32_t k_lm) {
#pragma unroll
        for (int i = 0; i < 4; i++) { sacc[i][0] = sacc[i][1] = sacc[i][2] = sacc[i][3] = 0.f; }
#pragma unroll
        for (int ks = 0; ks < 8; ks++) {
            uint32_t af[2][4], bf[2][2];
#pragma unroll
            for (int mt = 0; mt < 2; mt++)
                ldsm_x4(af[mt], q_lm + (uint32_t)(mt * 16 * 272 + ks * 32));
            {
                uint32_t t4[4];
                ldsm_x4(t4, k_lm + (uint32_t)(ks * 32));
                bf[0][0] = t4[0]; bf[0][1] = t4[1];
                bf[1][0] = t4[2]; bf[1][1] = t4[3];
            }
#pragma unroll
            for (int mt = 0; mt < 2; mt++)
#pragma unroll
                for (int nt = 0; nt < 2; nt++)
                    mma_f16(sacc[mt * 2 + nt], af[mt], bf[nt]);
        }
    };

    {
        const __half* qs = Qg + (size_t)crow * QKV_N + cbo / 2;
        const __half* ks = Kg + (size_t)crow * QKV_N + cbo / 2;
        const uint32_t qd = sb + AQ  + (uint32_t)crow * 272u + cbo;
        const uint32_t kd = sb + AK0 + (uint32_t)crow * 272u + cbo;
#pragma unroll
        for (int j = 0; j < 4; j++) cp_async16(qd + j * 16u, qs + j * 8);
#pragma unroll
        for (int j = 0; j < 4; j++) cp_async16(kd + j * 16u, ks + j * 8);
        cp_commit();

        const __half* vs = Vg + (size_t)crow * QKV_N + cbo / 2;
        const __half* k1 = Kg + (size_t)(BC + crow) * QKV_N + cbo / 2;
        const uint32_t vd = sb + AV0 + (uint32_t)crow * 272u + cbo;
        const uint32_t k1d = sb + AK1 + (uint32_t)crow * 272u + cbo;
#pragma unroll
        for (int j = 0; j < 4; j++) cp_async16(vd + j * 16u, vs + j * 8);
#pragma unroll
        for (int j = 0; j < 4; j++) cp_async16(k1d + j * 16u, k1 + j * 8);
        cp_commit();
    }
    if (tid < BR) { m_s[tid] = -INFINITY; l_s[tid] = 0.f; }

    cp_wait<1>();
    __syncthreads();

    compute_S(sb + AK0 + k_lmBo);

    for (int t = 0; t < NT; ++t) {
        const int cur = t & 1, nxt = cur ^ 1;

#pragma unroll
        for (int mt = 0; mt < 2; mt++)
#pragma unroll
            for (int hh = 0; hh < 2; hh++) {
                float a0 = sacc[2 * mt][2 * hh],     a1 = sacc[2 * mt][2 * hh + 1];
                float a2 = sacc[2 * mt + 1][2 * hh], a3 = sacc[2 * mt + 1][2 * hh + 1];
                float mx = fmaxf(fmaxf(a0, a1), fmaxf(a2, a3));
                mx = fmaxf(mx, __shfl_xor_sync(0xffffffffu, mx, 1));
                mx = fmaxf(mx, __shfl_xor_sync(0xffffffffu, mx, 2));
                if (tig == 0) pmax[wN * 64 + 32 * wM + 16 * mt + g + 8 * hh] = mx;
            }
        __syncthreads();

        float corr[2][2];
#pragma unroll
        for (int mt = 0; mt < 2; mt++)
#pragma unroll
            for (int hh = 0; hh < 2; hh++) {
                const int r = 32 * wM + 16 * mt + g + 8 * hh;
                const float mold = m_s[cur * 64 + r];
                float mn = fmaxf(fmaxf(pmax[r], pmax[64 + r]),
                                 fmaxf(pmax[128 + r], pmax[192 + r]));
                mn = fmaxf(mold, mn);
                const float co = fast_exp(mold - mn);
                corr[mt][hh] = co;
                if (wN == 0 && tig == 0) m_s[nxt * 64 + r] = mn;

                float e0 = fast_exp(sacc[2 * mt][2 * hh] - mn);
                float e1 = fast_exp(sacc[2 * mt][2 * hh + 1] - mn);
                float e2 = fast_exp(sacc[2 * mt + 1][2 * hh] - mn);
                float e3 = fast_exp(sacc[2 * mt + 1][2 * hh + 1] - mn);
                float sum = (e0 + e1) + (e2 + e3);
                sum += __shfl_xor_sync(0xffffffffu, sum, 1);
                sum += __shfl_xor_sync(0xffffffffu, sum, 2);
                if (tig == 0) psum[wN * 64 + r] = sum;

                char* pr = smc + AP + (size_t)r * 144;
                *(__half2*)(pr + (16 * wN + 2 * tig) * 2)     = __floats2half2_rn(e0, e1);
                *(__half2*)(pr + (16 * wN + 8 + 2 * tig) * 2) = __floats2half2_rn(e2, e3);
            }

        cp_wait<0>();
        __syncthreads();

        if (wN == 0 && tig == 0) {
#pragma unroll
            for (int mt = 0; mt < 2; mt++)
#pragma unroll
                for (int hh = 0; hh < 2; hh++) {
                    const int r = 32 * wM + 16 * mt + g + 8 * hh;
                    l_s[nxt * 64 + r] = l_s[cur * 64 + r] * corr[mt][hh] +
                        ((psum[r] + psum[64 + r]) + (psum[128 + r] + psum[192 + r]));
                }
        }

        if (t + 1 < NT) {
            const __half* vs = Vg + (size_t)((t + 1) * BC + crow) * QKV_N + cbo / 2;
            const uint32_t vd = sb + (nxt ? AV1 : AV0) + (uint32_t)crow * 272u + cbo;
#pragma unroll
            for (int j = 0; j < 4; j++) cp_async16(vd + j * 16u, vs + j * 8);
            if (t + 2 < NT) {
                const __half* ks = Kg + (size_t)((t + 2) * BC + crow) * QKV_N + cbo / 2;
                const uint32_t kd = sb + (cur ? AK1 : AK0) + (uint32_t)crow * 272u + cbo;
#pragma unroll
                for (int j = 0; j < 4; j++) cp_async16(kd + j * 16u, ks + j * 8);
            }
            cp_commit();
        }

#pragma unroll
        for (int mt = 0; mt < 2; mt++)
#pragma unroll
            for (int nt = 0; nt < 4; nt++) {
                float* a = oacc[mt * 4 + nt];
                a[0] *= corr[mt][0]; a[1] *= corr[mt][0];
                a[2] *= corr[mt][1]; a[3] *= corr[mt][1];
            }

        const uint32_t v_lm = sb + (cur ? AV1 : AV0) + lpA272;
#pragma unroll
        for (int ks = 0; ks < 4; ks++) {
            uint32_t paf[2][4], vbf[4][2];
#pragma unroll
            for (int mt = 0; mt < 2; mt++)
                ldsm_x4(paf[mt], p_lm + (uint32_t)(mt * 16 * 144 + ks * 32));
#pragma unroll
            for (int ng = 0; ng < 2; ng++) {
                uint32_t t4[4];
                ldsm_x4_t(t4, v_lm + (uint32_t)(ks * 16 * 272 + (32 * wN + ng * 16) * 2));
                vbf[2 * ng][0]     = t4[0];
                vbf[2 * ng][1]     = t4[1];
                vbf[2 * ng + 1][0] = t4[2];
                vbf[2 * ng + 1][1] = t4[3];
            }
#pragma unroll
            for (int mt = 0; mt < 2; mt++)
#pragma unroll
                for (int nt = 0; nt < 4; nt++)
                    mma_f16(oacc[mt * 4 + nt], paf[mt], vbf[nt]);
        }

        if (t + 1 < NT)
            compute_S(sb + (nxt ? AK1 : AK0) + k_lmBo);
    }

    __syncthreads();
    const int fin = NT & 1;
#pragma unroll
    for (int mt = 0; mt < 2; mt++) {
        const int r0 = 32 * wM + 16 * mt + g;
        const float il0 = 1.f / l_s[fin * 64 + r0];
        const float il1 = 1.f / l_s[fin * 64 + r0 + 8];
#pragma unroll
        for (int nt = 0; nt < 4; nt++) {
            const int col = h * HDIM + 32 * wN + 8 * nt + 2 * tig;
            *(__half2*)(xo + (size_t)(q0 + r0) * DIM + col) =
                __floats2half2_rn(oacc[mt * 4 + nt][0] * il0, oacc[mt * 4 + nt][1] * il0);
            *(__half2*)(xo + (size_t)(q0 + r0 + 8) * DIM + col) =
                __floats2half2_rn(oacc[mt * 4 + nt][2] * il1, oacc[mt * 4 + nt][3] * il1);
        }
    }
}

// ---------------------------------------------------------------------------
// Launch
// ---------------------------------------------------------------------------
extern "C" void kernel_launch(void* const* d_in, const int* in_sizes, int n_in,
                              void* d_out, int out_size)
{
    const float* x    = (const float*)d_in[0];   // [4096, 2048]
    const float* Wqkv = (const float*)d_in[1];   // [2048, 6144]
    const float* Wo   = (const float*)d_in[2];   // [2048, 2048]
    float* out = (float*)d_out;                  // [4096, 2048]

    __half *xh, *wqkvT, *woT, *xqkv, *xo;
    cudaGetSymbolAddress((void**)&xh,    g_xh);
    cudaGetSymbolAddress((void**)&wqkvT, g_wqkvT);
    cudaGetSymbolAddress((void**)&woT,   g_woT);
    cudaGetSymbolAddress((void**)&xqkv,  g_xqkv);
    cudaGetSymbolAddress((void**)&xo,    g_xo);

    cudaFuncSetAttribute(gemm_f16, cudaFuncAttributeMaxDynamicSharedMemorySize,
                         GEMM_SMEM_BYTES);
    cudaFuncSetAttribute(attn_f16, cudaFuncAttributeMaxDynamicSharedMemorySize,
                         ATTN_SMEM_BYTES);

    // 0) prep
    f2h_kernel<<<(SEQ * DIM / 4) / 256, 256>>>(x, xh, SEQ * DIM / 4);
    {
        dim3 blk(32, 8);
        transpose_h_kernel<<<dim3(QKV_N / 32, DIM / 32), blk>>>(
            Wqkv, wqkvT, DIM, QKV_N, NHEADS * HDIM, 0.08838834764831845f);
        transpose_h_kernel<<<dim3(DIM / 32, DIM / 32), blk>>>(
            Wo, woT, DIM, DIM, 0, 1.0f);
    }
    // 1) xqkv = x @ Wqkv (fp16 out); grid x = N-blocks for L2 sharing of A
    {
        dim3 grid(QKV_N / 64, SEQ / 128);
        gemm_f16<<<grid, 256, GEMM_SMEM_BYTES>>>(xh, wqkvT, xqkv, QKV_N, DIM, 1);
    }
    // 2) flash attention -> xo (fp16)
    {
        dim3 grid(SEQ / BR, NHEADS);
        attn_f16<<<grid, 256, ATTN_SMEM_BYTES>>>(xqkv, xo);
    }
    // 3) out = xo @ Wo (fp32 out)
    {
        dim3 grid(DIM / 64, SEQ / 128);
        gemm_f16<<<grid, 256, GEMM_SMEM_BYTES>>>(xo, woT, out, DIM, DIM, 0);
    }
}